// round 4
// baseline (speedup 1.0000x reference)
#include <cuda_runtime.h>
#include <cuda_bf16.h>
#include <cstdint>
#include <cstring>

#define DI __device__ __forceinline__

// ---------------- static scratch (no allocation allowed) ----------------
__device__ __align__(16) __nv_bfloat16 g_poolbf[31457280]; // pooled bf16, 4 levels packed
__device__ __align__(16) __nv_bfloat16 g_sW[1966080];      // g1*W1 bf16 [C][512] per level
__device__ float g_rstats[4 * 8192 * 2];                   // per-row sum, sumsq (pooled part)
__device__ float g_proto_mean[4 * 2048];
__device__ float g_s2ss2[8];                               // per level: sum, sumsq of proto ctx
__device__ float g_part[30 * 1536];                        // gw/bw/u2 partials per j-chunk
__device__ float g_gw[2048], g_bw[2048], g_u2[2048];
__device__ float g_text[4096];                             // l2-normalized text [8][512]
__device__ float g_logits[8192 * 32];                      // [B][4][8] pre-scale logits

__constant__ int cC[4]  = {256, 512, 1024, 2048};
__constant__ int cPO[4] = {0, 2097152, 6291456, 14680064}; // bf16 elem offsets into g_poolbf
__constant__ int cWO[4] = {0, 131072, 393216, 917504};     // elem offsets into g_sW

// ---------------- PTX helpers ----------------
DI uint32_t su32(const void* p) {
    uint32_t a;
    asm("{ .reg .u64 t; cvta.to.shared.u64 t, %1; cvt.u32.u64 %0, t; }" : "=r"(a) : "l"(p));
    return a;
}
DI void cp16(uint32_t d, const void* s) {
    asm volatile("cp.async.cg.shared.global [%0], [%1], 16;" :: "r"(d), "l"(s));
}
DI void cpcommit() { asm volatile("cp.async.commit_group;"); }
DI void ldmA(uint32_t* r, uint32_t a) {
    asm volatile("ldmatrix.sync.aligned.m8n8.x4.shared.b16 {%0,%1,%2,%3}, [%4];"
                 : "=r"(r[0]), "=r"(r[1]), "=r"(r[2]), "=r"(r[3]) : "r"(a));
}
DI void ldmBT(uint32_t* r, uint32_t a) {
    asm volatile("ldmatrix.sync.aligned.m8n8.x4.trans.shared.b16 {%0,%1,%2,%3}, [%4];"
                 : "=r"(r[0]), "=r"(r[1]), "=r"(r[2]), "=r"(r[3]) : "r"(a));
}
DI void mma16816(float* c, const uint32_t* a, const uint32_t* b) {
    asm volatile(
        "mma.sync.aligned.m16n8k16.row.col.f32.bf16.bf16.f32 "
        "{%0,%1,%2,%3}, {%4,%5,%6,%7}, {%8,%9}, {%0,%1,%2,%3};"
        : "+f"(c[0]), "+f"(c[1]), "+f"(c[2]), "+f"(c[3])
        : "r"(a[0]), "r"(a[1]), "r"(a[2]), "r"(a[3]), "r"(b[0]), "r"(b[1]));
}

// ---------------- precompute kernels ----------------
__global__ void k_proto(const float* __restrict__ p0, const float* __restrict__ p1,
                        const float* __restrict__ p2, const float* __restrict__ p3) {
    const float* pr[4] = {p0, p1, p2, p3};
    const int lvl = blockIdx.x, C = cC[lvl];
    const float* P = pr[lvl];
    __shared__ float r1[256], r2[256];
    float s2 = 0.f, ss2 = 0.f;
    for (int c = threadIdx.x; c < C; c += 256) {
        float s = 0.f;
        #pragma unroll 4
        for (int p = 0; p < 64; p++) s += P[p * C + c];
        const float pm = s * 0.015625f;
        g_proto_mean[lvl * 2048 + c] = pm;
        s2 += pm; ss2 += pm * pm;
    }
    r1[threadIdx.x] = s2; r2[threadIdx.x] = ss2; __syncthreads();
    for (int o = 128; o; o >>= 1) {
        if (threadIdx.x < o) { r1[threadIdx.x] += r1[threadIdx.x + o]; r2[threadIdx.x] += r2[threadIdx.x + o]; }
        __syncthreads();
    }
    if (!threadIdx.x) { g_s2ss2[lvl * 2] = r1[0]; g_s2ss2[lvl * 2 + 1] = r2[0]; }
}

__global__ void k_text(const float* __restrict__ tb) {
    const int w = threadIdx.x >> 5, ln = threadIdx.x & 31;
    float4 v[4]; float ss = 0.f;
    #pragma unroll
    for (int j = 0; j < 4; j++) {
        v[j] = *(const float4*)(tb + w * 512 + ln * 4 + j * 128);
        ss += v[j].x * v[j].x + v[j].y * v[j].y + v[j].z * v[j].z + v[j].w * v[j].w;
    }
    #pragma unroll
    for (int o = 16; o; o >>= 1) ss += __shfl_xor_sync(~0u, ss, o);
    const float inv = 1.f / fmaxf(sqrtf(ss), 1e-12f);
    #pragma unroll
    for (int j = 0; j < 4; j++) {
        float4 u = v[j]; u.x *= inv; u.y *= inv; u.z *= inv; u.w *= inv;
        *(float4*)(g_text + w * 512 + ln * 4 + j * 128) = u;
    }
}

// pooled fp32 -> bf16 + per-row stats. one warp per row.
__global__ void k_pool(const float* p0, const float* p1, const float* p2, const float* p3) {
    const float* pp[4] = {p0, p1, p2, p3};
    const int w = blockIdx.x * 8 + (threadIdx.x >> 5), ln = threadIdx.x & 31;
    const int lvl = w >> 13, row = w & 8191;
    const int C = cC[lvl];
    const float* src = pp[lvl] + (size_t)row * C;
    __nv_bfloat16* dst = g_poolbf + cPO[lvl] + (size_t)row * C;
    float s = 0.f, q = 0.f;
    for (int d = ln * 4; d < C; d += 128) {
        const float4 v = *(const float4*)(src + d);
        s += v.x + v.y + v.z + v.w;
        q = fmaf(v.x, v.x, q); q = fmaf(v.y, v.y, q);
        q = fmaf(v.z, v.z, q); q = fmaf(v.w, v.w, q);
        __nv_bfloat162 a = __floats2bfloat162_rn(v.x, v.y);
        __nv_bfloat162 b = __floats2bfloat162_rn(v.z, v.w);
        uint2 u; memcpy(&u.x, &a, 4); memcpy(&u.y, &b, 4);
        *(uint2*)(dst + d) = u;
    }
    #pragma unroll
    for (int o = 16; o; o >>= 1) {
        s += __shfl_xor_sync(~0u, s, o);
        q += __shfl_xor_sync(~0u, q, o);
    }
    if (!ln) {
        g_rstats[(lvl * 8192 + row) * 2] = s;
        g_rstats[(lvl * 8192 + row) * 2 + 1] = q;
    }
}

struct WPtr { const float* W[4]; const float* g[4]; const float* bb[4]; };

// per 256-row j-chunk: partials of gw/bw/u2 + emit scaled W1 bf16 rows
__global__ void k_wb(WPtr P) {
    const int cb = blockIdx.x;
    const int lvl = cb < 2 ? 0 : cb < 6 ? 1 : cb < 14 ? 2 : 3;
    const int base4[4] = {0, 2, 6, 14};
    const int j0 = (cb - base4[lvl]) * 256;
    const int C = cC[lvl];
    const int c0 = threadIdx.x * 2;
    const float* W = P.W[lvl];
    const float* gg = P.g[lvl];
    const float* bv = P.bb[lvl];
    float gw0 = 0, gw1 = 0, bw0 = 0, bw1 = 0, u0 = 0, u1 = 0;
    for (int jj = 0; jj < 256; jj++) {
        const int j = j0 + jj;
        const float gj = gg[j], bj = bv[j];
        const float2 w2 = *(const float2*)(W + (size_t)j * 512 + c0);
        gw0 = fmaf(gj, w2.x, gw0); gw1 = fmaf(gj, w2.y, gw1);
        bw0 = fmaf(bj, w2.x, bw0); bw1 = fmaf(bj, w2.y, bw1);
        if (j >= C) {
            const float pj = g_proto_mean[lvl * 2048 + (j - C)] * gj;
            u0 = fmaf(pj, w2.x, u0); u1 = fmaf(pj, w2.y, u1);
        } else {
            __nv_bfloat162 h = __floats2bfloat162_rn(gj * w2.x, gj * w2.y);
            uint32_t hu; memcpy(&hu, &h, 4);
            *(uint32_t*)(g_sW + cWO[lvl] + (size_t)j * 512 + c0) = hu;
        }
    }
    float* pt = g_part + cb * 1536;
    pt[c0] = gw0; pt[c0 + 1] = gw1;
    pt[512 + c0] = bw0; pt[512 + c0 + 1] = bw1;
    pt[1024 + c0] = u0; pt[1024 + c0 + 1] = u1;
}

__global__ void k_wbred(const float* b0, const float* b1, const float* b2, const float* b3) {
    const float* bs[4] = {b0, b1, b2, b3};
    const int lvl = blockIdx.x, d = threadIdx.x;
    const int base4[4] = {0, 2, 6, 14}, cnt4[4] = {2, 4, 8, 16};
    float gw = 0, bw = 0, u = 0;
    for (int c = base4[lvl]; c < base4[lvl] + cnt4[lvl]; c++) {
        const float* pt = g_part + c * 1536;
        gw += pt[d]; bw += pt[512 + d]; u += pt[1024 + d];
    }
    g_gw[lvl * 512 + d] = gw;
    g_bw[lvl * 512 + d] = bw + bs[lvl][d];
    g_u2[lvl * 512 + d] = u;
}

// ---------------- main fused GEMM + epilogue ----------------
// CTA: 64 rows x 512 cols, BK=32, 8 warps (each warp n-slice of 64), 2-stage cp.async.
__global__ void __launch_bounds__(256, 1) k_main() {
    extern __shared__ char smem[];
    const uint32_t sb = su32(smem);
    const int tid = threadIdx.x, wid = tid >> 5, lane = tid & 31;
    const int lvl = 3 - (blockIdx.x >> 7);      // big levels first
    const int tile = blockIdx.x & 127;
    const int C = cC[lvl];
    const int nch = C >> 5;
    const int row0 = tile * 64;
    const __nv_bfloat16* Ag = g_poolbf + cPO[lvl] + (size_t)row0 * C;
    const __nv_bfloat16* Bg = g_sW + cWO[lvl];

    // A cp.async: thread t -> row t/4, 16B chunk t%4 (rows padded to 128B, SW swizzled)
    const int ar = tid >> 2, ac = tid & 3;
    const __nv_bfloat16* aSrcBase = Ag + (size_t)ar * C + ac * 8;
    const uint32_t aDst = sb + ar * 128 + ((ac * 16) ^ ((ar & 7) << 4));

    float acc[4][8][4];
    #pragma unroll
    for (int i = 0; i < 4; i++)
        #pragma unroll
        for (int j = 0; j < 8; j++)
            #pragma unroll
            for (int k = 0; k < 4; k++) acc[i][j][k] = 0.f;

    const int rbase = (lane & 7) + 8 * ((lane >> 3) & 1);
    const int cbmat = (lane >> 4) * 16;
    const int xorv = (rbase & 7) << 4;

    auto issue = [&](int ch) {
        const int st = ch & 1;
        cp16(aDst + st * 8192, aSrcBase + ch * 32);
        const __nv_bfloat16* bp = Bg + (size_t)(ch * 32) * 512;
        #pragma unroll
        for (int i = 0; i < 8; i++) {
            const int c = tid + 256 * i, r = c >> 6, c16 = c & 63;
            cp16(sb + 16384 + st * 32768 + r * 1024 + ((c16 * 16) ^ ((r & 7) << 4)),
                 bp + r * 512 + c16 * 8);
        }
        cpcommit();
    };

    issue(0);
    for (int ch = 0; ch < nch; ch++) {
        if (ch + 1 < nch) { issue(ch + 1); asm volatile("cp.async.wait_group 1;"); }
        else              { asm volatile("cp.async.wait_group 0;"); }
        __syncthreads();
        const int st = ch & 1;
        const uint32_t sA = sb + st * 8192;
        const uint32_t sB = sb + 16384 + st * 32768;
        #pragma unroll
        for (int ks = 0; ks < 2; ks++) {
            uint32_t bf[4][4], af[4][4];
            #pragma unroll
            for (int np = 0; np < 4; np++)
                ldmBT(bf[np], sB + (ks * 16 + rbase) * 1024 +
                              ((((wid * 64 + np * 16) * 2) + cbmat) ^ xorv));
            #pragma unroll
            for (int mt = 0; mt < 4; mt++)
                ldmA(af[mt], sA + (mt * 16 + rbase) * 128 + (((ks * 32) + cbmat) ^ xorv));
            #pragma unroll
            for (int mt = 0; mt < 4; mt++)
                #pragma unroll
                for (int nt = 0; nt < 8; nt++)
                    mma16816(acc[mt][nt], af[mt], &bf[nt >> 1][(nt & 1) * 2]);
        }
        __syncthreads();
    }

    // -------- epilogue --------
    float* sf = (float*)smem;
    float* Hs  = sf;               // [64][520] fp32, reuses mainloop smem
    float* txs = sf + 33280;       // [8][512]
    float* u2s = sf + 37376;
    float* gws = u2s + 512;
    float* bws = gws + 512;
    float2* srs = (float2*)(bws + 512);  // [64] (mean, inv)

    for (int i = tid; i < 4096; i += 256) txs[i] = g_text[i];
    for (int i = tid; i < 512; i += 256) {
        u2s[i] = g_u2[lvl * 512 + i];
        gws[i] = g_gw[lvl * 512 + i];
        bws[i] = g_bw[lvl * 512 + i];
    }
    if (tid < 64) {
        const float s = g_rstats[(lvl * 8192 + row0 + tid) * 2] + g_s2ss2[lvl * 2];
        const float q = g_rstats[(lvl * 8192 + row0 + tid) * 2 + 1] + g_s2ss2[lvl * 2 + 1];
        const float invN = 1.f / (float)(2 * C);
        const float m = s * invN;
        const float var = q * invN - m * m;
        srs[tid] = make_float2(m, rsqrtf(var + 1e-5f));
    }
    __syncthreads();

    // pass 1: h = relu(inv*(Y + u2 - m*gw) + bw) -> Hs
    const int cb0 = wid * 64 + (lane & 3) * 2;
    const int rr0 = lane >> 2;
    #pragma unroll
    for (int mt = 0; mt < 4; mt++) {
        const float2 s0 = srs[mt * 16 + rr0];
        const float2 s1 = srs[mt * 16 + rr0 + 8];
        #pragma unroll
        for (int nt = 0; nt < 8; nt++) {
            const int c = cb0 + nt * 8;
            const float u2a = u2s[c], u2b = u2s[c + 1];
            const float gwa = gws[c], gwb = gws[c + 1];
            const float bwa = bws[c], bwb = bws[c + 1];
            const float h0 = fmaxf(s0.y * (acc[mt][nt][0] + u2a - s0.x * gwa) + bwa, 0.f);
            const float h1 = fmaxf(s0.y * (acc[mt][nt][1] + u2b - s0.x * gwb) + bwb, 0.f);
            const float h2 = fmaxf(s1.y * (acc[mt][nt][2] + u2a - s1.x * gwa) + bwa, 0.f);
            const float h3 = fmaxf(s1.y * (acc[mt][nt][3] + u2b - s1.x * gwb) + bwb, 0.f);
            *(float2*)(Hs + (mt * 16 + rr0) * 520 + c)     = make_float2(h0, h1);
            *(float2*)(Hs + (mt * 16 + rr0 + 8) * 520 + c) = make_float2(h2, h3);
        }
    }
    __syncthreads();

    // pass 2: per-row ||h|| and 8 text dots; warp w -> rows 8w..8w+7
    for (int rr = 0; rr < 8; rr++) {
        const int r = wid * 8 + rr;
        const float* hr = Hs + r * 520;
        float ss = 0.f;
        float dk[8] = {0, 0, 0, 0, 0, 0, 0, 0};
        #pragma unroll
        for (int j = 0; j < 4; j++) {
            const int d = lane * 4 + j * 128;
            const float4 h4 = *(const float4*)(hr + d);
            ss = fmaf(h4.x, h4.x, ss); ss = fmaf(h4.y, h4.y, ss);
            ss = fmaf(h4.z, h4.z, ss); ss = fmaf(h4.w, h4.w, ss);
            #pragma unroll
            for (int k = 0; k < 8; k++) {
                const float4 t4 = *(const float4*)(txs + k * 512 + d);
                dk[k] += h4.x * t4.x + h4.y * t4.y + h4.z * t4.z + h4.w * t4.w;
            }
        }
        #pragma unroll
        for (int o = 16; o; o >>= 1) {
            ss += __shfl_xor_sync(~0u, ss, o);
            #pragma unroll
            for (int k = 0; k < 8; k++) dk[k] += __shfl_xor_sync(~0u, dk[k], o);
        }
        if (!lane) {
            const float invn = 1.f / fmaxf(sqrtf(ss), 1e-12f);
            float* dst = g_logits + (size_t)(row0 + r) * 32 + lvl * 8;
            #pragma unroll
            for (int k = 0; k < 8; k++) dst[k] = dk[k] * invn;
        }
    }
}

// ---------------- final softmax over L ----------------
__global__ void k_fin(const float* __restrict__ ls, float* __restrict__ out) {
    const int i = blockIdx.x * 256 + threadIdx.x;  // b*8 + k
    const float s = fmaxf(ls[0], 1e-4f) * 0.044194173824159216f;  // clip * 1/sqrt(512)
    const int b = i >> 3, k = i & 7;
    float z[4], mx = -1e30f;
    #pragma unroll
    for (int l = 0; l < 4; l++) {
        z[l] = g_logits[b * 32 + l * 8 + k] * s;
        mx = fmaxf(mx, z[l]);
    }
    float e[4], sum = 0.f;
    #pragma unroll
    for (int l = 0; l < 4; l++) { e[l] = expf(z[l] - mx); sum += e[l]; }
    const float inv = 1.f / sum;
    #pragma unroll
    for (int l = 0; l < 4; l++) out[i * 4 + l] = e[l] * inv;
}

// ---------------- launch ----------------
extern "C" void kernel_launch(void* const* d_in, const int* in_sizes, int n_in,
                              void* d_out, int out_size) {
    const float *pooled[4], *proto[4], *lng[4], *lnb[4], *W[4], *bias[4];
    const bool interleaved = (in_sizes[1] == 16384);  // proto_0 = 64*256
    for (int i = 0; i < 4; i++) {
        if (interleaved) {
            pooled[i] = (const float*)d_in[6 * i + 0];
            proto[i]  = (const float*)d_in[6 * i + 1];
            lng[i]    = (const float*)d_in[6 * i + 2];
            lnb[i]    = (const float*)d_in[6 * i + 3];
            W[i]      = (const float*)d_in[6 * i + 4];
            bias[i]   = (const float*)d_in[6 * i + 5];
        } else {
            pooled[i] = (const float*)d_in[i];
            proto[i]  = (const float*)d_in[4 + i];
            lng[i]    = (const float*)d_in[8 + i];
            lnb[i]    = (const float*)d_in[12 + i];
            W[i]      = (const float*)d_in[16 + i];
            bias[i]   = (const float*)d_in[20 + i];
        }
    }
    const float* text = (const float*)d_in[24];
    const float* ls   = (const float*)d_in[25];

    k_proto<<<4, 256>>>(proto[0], proto[1], proto[2], proto[3]);
    k_text<<<1, 256>>>(text);
    k_pool<<<4096, 256>>>(pooled[0], pooled[1], pooled[2], pooled[3]);
    WPtr wp;
    for (int i = 0; i < 4; i++) { wp.W[i] = W[i]; wp.g[i] = lng[i]; wp.bb[i] = lnb[i]; }
    k_wb<<<30, 256>>>(wp);
    k_wbred<<<4, 512>>>(bias[0], bias[1], bias[2], bias[3]);

    cudaFuncSetAttribute(k_main, cudaFuncAttributeMaxDynamicSharedMemorySize, 156160);
    k_main<<<512, 256, 156160>>>();
    k_fin<<<256, 256>>>(ls, (float*)d_out);
}

// round 5
// speedup vs baseline: 2.1943x; 2.1943x over previous
#include <cuda_runtime.h>
#include <cuda_bf16.h>
#include <cstdint>
#include <cstring>

#define DI __device__ __forceinline__

// ---------------- static scratch (no allocation allowed) ----------------
__device__ __align__(16) __nv_bfloat16 g_poolbf[31457280]; // pooled bf16, 4 levels packed
__device__ __align__(16) __nv_bfloat16 g_sW[1966080];      // g1*W1 bf16 [C][512] per level
__device__ float g_rstats[4 * 8192 * 2];                   // per-row sum, sumsq (pooled part)
__device__ float g_proto_mean[4 * 2048];
__device__ float g_s2ss2[8];                               // per level: sum, sumsq of proto ctx
__device__ float g_gw[2048], g_bw[2048], g_u2[2048];
__device__ float g_text[4096];                             // l2-normalized text [8][512]
__device__ float g_logits[8192 * 32];                      // [B][4][8] pre-scale logits

__constant__ int cC[4]  = {256, 512, 1024, 2048};
__constant__ int cPO[4] = {0, 2097152, 6291456, 14680064}; // bf16 elem offsets into g_poolbf
__constant__ int cWO[4] = {0, 131072, 393216, 917504};     // elem offsets into g_sW

// ---------------- PTX helpers ----------------
DI uint32_t su32(const void* p) {
    uint32_t a;
    asm("{ .reg .u64 t; cvta.to.shared.u64 t, %1; cvt.u32.u64 %0, t; }" : "=r"(a) : "l"(p));
    return a;
}
DI void cp16(uint32_t d, const void* s) {
    asm volatile("cp.async.cg.shared.global [%0], [%1], 16;" :: "r"(d), "l"(s));
}
DI void cpcommit() { asm volatile("cp.async.commit_group;"); }
DI void ldmA(uint32_t* r, uint32_t a) {
    asm volatile("ldmatrix.sync.aligned.m8n8.x4.shared.b16 {%0,%1,%2,%3}, [%4];"
                 : "=r"(r[0]), "=r"(r[1]), "=r"(r[2]), "=r"(r[3]) : "r"(a));
}
DI void ldmBT(uint32_t* r, uint32_t a) {
    asm volatile("ldmatrix.sync.aligned.m8n8.x4.trans.shared.b16 {%0,%1,%2,%3}, [%4];"
                 : "=r"(r[0]), "=r"(r[1]), "=r"(r[2]), "=r"(r[3]) : "r"(a));
}
DI void mma16816(float* c, const uint32_t* a, const uint32_t* b) {
    asm volatile(
        "mma.sync.aligned.m16n8k16.row.col.f32.bf16.bf16.f32 "
        "{%0,%1,%2,%3}, {%4,%5,%6,%7}, {%8,%9}, {%0,%1,%2,%3};"
        : "+f"(c[0]), "+f"(c[1]), "+f"(c[2]), "+f"(c[3])
        : "r"(a[0]), "r"(a[1]), "r"(a[2]), "r"(a[3]), "r"(b[0]), "r"(b[1]));
}

// ---------------- precompute kernels ----------------
// zero accumulators + seed g_bw with bias
__global__ void k_zero(const float* b0, const float* b1, const float* b2, const float* b3) {
    const float* bs[4] = {b0, b1, b2, b3};
    const int lvl = blockIdx.x, d = threadIdx.x;
    g_gw[lvl * 512 + d] = 0.f;
    g_u2[lvl * 512 + d] = 0.f;
    g_bw[lvl * 512 + d] = bs[lvl][d];
    if (lvl == 0 && d < 8) g_s2ss2[d] = 0.f;
}

// proto mean per column; 15 blocks of 256 cols
__global__ void k_proto(const float* __restrict__ p0, const float* __restrict__ p1,
                        const float* __restrict__ p2, const float* __restrict__ p3) {
    const float* pr[4] = {p0, p1, p2, p3};
    const int cb = blockIdx.x;
    const int lvl = cb < 1 ? 0 : cb < 3 ? 1 : cb < 7 ? 2 : 3;
    const int base4[4] = {0, 1, 3, 7};
    const int C = cC[lvl];
    const int c = (cb - base4[lvl]) * 256 + threadIdx.x;
    const float* P = pr[lvl];
    float s = 0.f;
    #pragma unroll 8
    for (int p = 0; p < 64; p++) s += P[p * C + c];
    const float pm = s * 0.015625f;
    g_proto_mean[lvl * 2048 + c] = pm;
    // block-level reduction of sum / sumsq
    __shared__ float r1[256], r2[256];
    r1[threadIdx.x] = pm; r2[threadIdx.x] = pm * pm; __syncthreads();
    for (int o = 128; o; o >>= 1) {
        if (threadIdx.x < o) { r1[threadIdx.x] += r1[threadIdx.x + o]; r2[threadIdx.x] += r2[threadIdx.x + o]; }
        __syncthreads();
    }
    if (!threadIdx.x) {
        atomicAdd(&g_s2ss2[lvl * 2], r1[0]);
        atomicAdd(&g_s2ss2[lvl * 2 + 1], r2[0]);
    }
}

__global__ void k_text(const float* __restrict__ tb) {
    const int w = threadIdx.x >> 5, ln = threadIdx.x & 31;
    float4 v[4]; float ss = 0.f;
    #pragma unroll
    for (int j = 0; j < 4; j++) {
        v[j] = *(const float4*)(tb + w * 512 + ln * 4 + j * 128);
        ss += v[j].x * v[j].x + v[j].y * v[j].y + v[j].z * v[j].z + v[j].w * v[j].w;
    }
    #pragma unroll
    for (int o = 16; o; o >>= 1) ss += __shfl_xor_sync(~0u, ss, o);
    const float inv = 1.f / fmaxf(sqrtf(ss), 1e-12f);
    #pragma unroll
    for (int j = 0; j < 4; j++) {
        float4 u = v[j]; u.x *= inv; u.y *= inv; u.z *= inv; u.w *= inv;
        *(float4*)(g_text + w * 512 + ln * 4 + j * 128) = u;
    }
}

// pooled fp32 -> bf16 + per-row stats. one warp per row.
__global__ void k_pool(const float* p0, const float* p1, const float* p2, const float* p3) {
    const float* pp[4] = {p0, p1, p2, p3};
    const int w = blockIdx.x * 8 + (threadIdx.x >> 5), ln = threadIdx.x & 31;
    const int lvl = w >> 13, row = w & 8191;
    const int C = cC[lvl];
    const float* src = pp[lvl] + (size_t)row * C;
    __nv_bfloat16* dst = g_poolbf + cPO[lvl] + (size_t)row * C;
    float s = 0.f, q = 0.f;
    for (int d = ln * 4; d < C; d += 128) {
        const float4 v = *(const float4*)(src + d);
        s += v.x + v.y + v.z + v.w;
        q = fmaf(v.x, v.x, q); q = fmaf(v.y, v.y, q);
        q = fmaf(v.z, v.z, q); q = fmaf(v.w, v.w, q);
        __nv_bfloat162 a = __floats2bfloat162_rn(v.x, v.y);
        __nv_bfloat162 b = __floats2bfloat162_rn(v.z, v.w);
        uint2 u; memcpy(&u.x, &a, 4); memcpy(&u.y, &b, 4);
        *(uint2*)(dst + d) = u;
    }
    #pragma unroll
    for (int o = 16; o; o >>= 1) {
        s += __shfl_xor_sync(~0u, s, o);
        q += __shfl_xor_sync(~0u, q, o);
    }
    if (!ln) {
        g_rstats[(lvl * 8192 + row) * 2] = s;
        g_rstats[(lvl * 8192 + row) * 2 + 1] = q;
    }
}

struct WPtr { const float* W[4]; const float* g[4]; const float* bb[4]; };

// per 32-row j-chunk (240 blocks): partials of gw/bw/u2 via atomics + scaled W1 bf16
__global__ void k_wb(WPtr P) {
    const int cb = blockIdx.x;
    const int lvl = cb < 16 ? 0 : cb < 48 ? 1 : cb < 112 ? 2 : 3;
    const int base4[4] = {0, 16, 48, 112};
    const int j0 = (cb - base4[lvl]) * 32;
    const int C = cC[lvl];
    const int c0 = threadIdx.x * 2;
    const float* W = P.W[lvl];
    const float* gg = P.g[lvl];
    const float* bv = P.bb[lvl];
    float gw0 = 0, gw1 = 0, bw0 = 0, bw1 = 0, u0 = 0, u1 = 0;
    #pragma unroll 4
    for (int jj = 0; jj < 32; jj++) {
        const int j = j0 + jj;
        const float gj = gg[j], bj = bv[j];
        const float2 w2 = *(const float2*)(W + (size_t)j * 512 + c0);
        gw0 = fmaf(gj, w2.x, gw0); gw1 = fmaf(gj, w2.y, gw1);
        bw0 = fmaf(bj, w2.x, bw0); bw1 = fmaf(bj, w2.y, bw1);
        if (j >= C) {
            const float pj = g_proto_mean[lvl * 2048 + (j - C)] * gj;
            u0 = fmaf(pj, w2.x, u0); u1 = fmaf(pj, w2.y, u1);
        } else {
            __nv_bfloat162 h = __floats2bfloat162_rn(gj * w2.x, gj * w2.y);
            uint32_t hu; memcpy(&hu, &h, 4);
            *(uint32_t*)(g_sW + cWO[lvl] + (size_t)j * 512 + c0) = hu;
        }
    }
    atomicAdd(&g_gw[lvl * 512 + c0], gw0);
    atomicAdd(&g_gw[lvl * 512 + c0 + 1], gw1);
    atomicAdd(&g_bw[lvl * 512 + c0], bw0);
    atomicAdd(&g_bw[lvl * 512 + c0 + 1], bw1);
    if (j0 >= C) {
        atomicAdd(&g_u2[lvl * 512 + c0], u0);
        atomicAdd(&g_u2[lvl * 512 + c0 + 1], u1);
    }
}

// ---------------- main fused GEMM + epilogue ----------------
// CTA: 64 rows x 512 cols, BK=32, 16 warps (warp = 32-col slice), 3-stage cp.async.
// smem: A 3x8KB @0, B 3x32KB @24576 -> 120KB
static constexpr int SM_B = 24576;
static constexpr int SM_TOTAL = 122880;

__global__ void __launch_bounds__(512, 1) k_main() {
    extern __shared__ char smem[];
    const uint32_t sb = su32(smem);
    const int tid = threadIdx.x, wid = tid >> 5, lane = tid & 31;
    const int lvl = 3 - (blockIdx.x >> 7);      // big levels first
    const int tile = blockIdx.x & 127;
    const int C = cC[lvl];
    const int nch = C >> 5;
    const int row0 = tile * 64;
    const __nv_bfloat16* Ag = g_poolbf + cPO[lvl] + (size_t)row0 * C;
    const __nv_bfloat16* Bg = g_sW + cWO[lvl];

    // A cp.async (threads 0..255): row t/4, 16B chunk t%4 (128B padded rows, swizzled)
    const int ar = tid >> 2, ac = tid & 3;
    const __nv_bfloat16* aSrcBase = Ag + (size_t)ar * C + ac * 8;
    const uint32_t aDst = sb + ar * 128 + ((ac * 16) ^ ((ar & 7) << 4));

    float acc[4][4][4];
    #pragma unroll
    for (int i = 0; i < 4; i++)
        #pragma unroll
        for (int j = 0; j < 4; j++)
            #pragma unroll
            for (int k = 0; k < 4; k++) acc[i][j][k] = 0.f;

    const int rbase = (lane & 7) + 8 * ((lane >> 3) & 1);
    const int cbmat = (lane >> 4) * 16;
    const int xorv = (rbase & 7) << 4;
    const int cb = wid * 32;

    auto issue = [&](int ch) {
        const int st = ch % 3;
        if (tid < 256) cp16(aDst + st * 8192, aSrcBase + ch * 32);
        const __nv_bfloat16* bp = Bg + (size_t)(ch * 32) * 512;
        #pragma unroll
        for (int i = 0; i < 4; i++) {
            const int c = tid + 512 * i, r = c >> 6, c16 = c & 63;
            cp16(sb + SM_B + st * 32768 + r * 1024 + ((c16 * 16) ^ ((r & 7) << 4)),
                 bp + r * 512 + c16 * 8);
        }
        cpcommit();
    };

    issue(0);
    if (nch > 1) issue(1);
    for (int ch = 0; ch < nch; ch++) {
        if (ch + 2 < nch) { issue(ch + 2); asm volatile("cp.async.wait_group 2;"); }
        else if (ch + 1 < nch) { asm volatile("cp.async.wait_group 1;"); }
        else { asm volatile("cp.async.wait_group 0;"); }
        __syncthreads();
        const int st = ch % 3;
        const uint32_t sA = sb + st * 8192;
        const uint32_t sB = sb + SM_B + st * 32768;
        #pragma unroll
        for (int ks = 0; ks < 2; ks++) {
            uint32_t bf[2][4], af[4][4];
            #pragma unroll
            for (int np = 0; np < 2; np++)
                ldmBT(bf[np], sB + (ks * 16 + rbase) * 1024 +
                              ((((cb + np * 16) * 2) + cbmat) ^ xorv));
            #pragma unroll
            for (int mt = 0; mt < 4; mt++)
                ldmA(af[mt], sA + (mt * 16 + rbase) * 128 + (((ks * 32) + cbmat) ^ xorv));
            #pragma unroll
            for (int mt = 0; mt < 4; mt++)
                #pragma unroll
                for (int nt = 0; nt < 4; nt++)
                    mma16816(acc[mt][nt], af[mt], &bf[nt >> 1][(nt & 1) * 2]);
        }
        __syncthreads();
    }

    // -------- epilogue (register-resident; reuses pipeline smem) --------
    float* sf   = (float*)smem;
    float* txs  = sf;                 // [8][512]
    float* u2s  = sf + 4096;
    float* gws  = u2s + 512;
    float* bws  = gws + 512;
    float2* srs = (float2*)(bws + 512);   // [64] (mean, inv)
    float* prp  = (float*)(srs + 64);     // [64 rows][16 warps][9]
    float* rinv = prp + 64 * 16 * 9;      // [64]

    for (int i = tid; i < 4096; i += 512) txs[i] = g_text[i];
    if (tid < 512) {
        u2s[tid] = g_u2[lvl * 512 + tid];
        gws[tid] = g_gw[lvl * 512 + tid];
        bws[tid] = g_bw[lvl * 512 + tid];
    }
    if (tid < 64) {
        const float s = g_rstats[(lvl * 8192 + row0 + tid) * 2] + g_s2ss2[lvl * 2];
        const float q = g_rstats[(lvl * 8192 + row0 + tid) * 2 + 1] + g_s2ss2[lvl * 2 + 1];
        const float invN = 1.f / (float)(2 * C);
        const float m = s * invN;
        const float var = q * invN - m * m;
        srs[tid] = make_float2(m, rsqrtf(var + 1e-5f));
    }
    __syncthreads();

    const int rr0 = lane >> 2;
    const int cq = (lane & 3) * 2;
    #pragma unroll
    for (int mt = 0; mt < 4; mt++) {
        const int r0 = mt * 16 + rr0, r1 = r0 + 8;
        const float2 s0 = srs[r0], s1 = srs[r1];
        float ss0 = 0.f, ss1 = 0.f;
        float dk0[8] = {0,0,0,0,0,0,0,0}, dk1[8] = {0,0,0,0,0,0,0,0};
        #pragma unroll
        for (int nt = 0; nt < 4; nt++) {
            const int c = cb + nt * 8 + cq;
            const float u2a = u2s[c], u2b = u2s[c + 1];
            const float gwa = gws[c], gwb = gws[c + 1];
            const float bwa = bws[c], bwb = bws[c + 1];
            const float h0 = fmaxf(s0.y * (acc[mt][nt][0] + u2a - s0.x * gwa) + bwa, 0.f);
            const float h1 = fmaxf(s0.y * (acc[mt][nt][1] + u2b - s0.x * gwb) + bwb, 0.f);
            const float h2 = fmaxf(s1.y * (acc[mt][nt][2] + u2a - s1.x * gwa) + bwa, 0.f);
            const float h3 = fmaxf(s1.y * (acc[mt][nt][3] + u2b - s1.x * gwb) + bwb, 0.f);
            ss0 = fmaf(h0, h0, ss0); ss0 = fmaf(h1, h1, ss0);
            ss1 = fmaf(h2, h2, ss1); ss1 = fmaf(h3, h3, ss1);
            #pragma unroll
            for (int k = 0; k < 8; k++) {
                const float2 t2 = *(const float2*)(txs + k * 512 + c);
                dk0[k] = fmaf(h0, t2.x, dk0[k]); dk0[k] = fmaf(h1, t2.y, dk0[k]);
                dk1[k] = fmaf(h2, t2.x, dk1[k]); dk1[k] = fmaf(h3, t2.y, dk1[k]);
            }
        }
        // quad reduce over lane&3 (same rows)
        #pragma unroll
        for (int o = 1; o < 4; o <<= 1) {
            ss0 += __shfl_xor_sync(~0u, ss0, o);
            ss1 += __shfl_xor_sync(~0u, ss1, o);
            #pragma unroll
            for (int k = 0; k < 8; k++) {
                dk0[k] += __shfl_xor_sync(~0u, dk0[k], o);
                dk1[k] += __shfl_xor_sync(~0u, dk1[k], o);
            }
        }
        if ((lane & 3) == 0) {
            float* p0 = prp + (r0 * 16 + wid) * 9;
            float* p1 = prp + (r1 * 16 + wid) * 9;
            p0[0] = ss0; p1[0] = ss1;
            #pragma unroll
            for (int k = 0; k < 8; k++) { p0[1 + k] = dk0[k]; p1[1 + k] = dk1[k]; }
        }
    }
    __syncthreads();
    if (tid < 64) {
        float ss = 0.f;
        #pragma unroll
        for (int w = 0; w < 16; w++) ss += prp[(tid * 16 + w) * 9];
        rinv[tid] = 1.f / fmaxf(sqrtf(ss), 1e-12f);
    }
    __syncthreads();
    {
        const int row = tid >> 3, k = tid & 7;
        float d = 0.f;
        #pragma unroll
        for (int w = 0; w < 16; w++) d += prp[(row * 16 + w) * 9 + 1 + k];
        g_logits[(size_t)(row0 + row) * 32 + lvl * 8 + k] = d * rinv[row];
    }
}

// ---------------- final softmax over L ----------------
__global__ void k_fin(const float* __restrict__ ls, float* __restrict__ out) {
    const int i = blockIdx.x * 256 + threadIdx.x;  // b*8 + k
    const float s = fmaxf(ls[0], 1e-4f) * 0.044194173824159216f;  // clip * 1/sqrt(512)
    const int b = i >> 3, k = i & 7;
    float z[4], mx = -1e30f;
    #pragma unroll
    for (int l = 0; l < 4; l++) {
        z[l] = g_logits[b * 32 + l * 8 + k] * s;
        mx = fmaxf(mx, z[l]);
    }
    float e[4], sum = 0.f;
    #pragma unroll
    for (int l = 0; l < 4; l++) { e[l] = expf(z[l] - mx); sum += e[l]; }
    const float inv = 1.f / sum;
    #pragma unroll
    for (int l = 0; l < 4; l++) out[i * 4 + l] = e[l] * inv;
}

// ---------------- launch ----------------
extern "C" void kernel_launch(void* const* d_in, const int* in_sizes, int n_in,
                              void* d_out, int out_size) {
    const float *pooled[4], *proto[4], *lng[4], *lnb[4], *W[4], *bias[4];
    const bool interleaved = (in_sizes[1] == 16384);  // proto_0 = 64*256
    for (int i = 0; i < 4; i++) {
        if (interleaved) {
            pooled[i] = (const float*)d_in[6 * i + 0];
            proto[i]  = (const float*)d_in[6 * i + 1];
            lng[i]    = (const float*)d_in[6 * i + 2];
            lnb[i]    = (const float*)d_in[6 * i + 3];
            W[i]      = (const float*)d_in[6 * i + 4];
            bias[i]   = (const float*)d_in[6 * i + 5];
        } else {
            pooled[i] = (const float*)d_in[i];
            proto[i]  = (const float*)d_in[4 + i];
            lng[i]    = (const float*)d_in[8 + i];
            lnb[i]    = (const float*)d_in[12 + i];
            W[i]      = (const float*)d_in[16 + i];
            bias[i]   = (const float*)d_in[20 + i];
        }
    }
    const float* text = (const float*)d_in[24];
    const float* ls   = (const float*)d_in[25];

    k_zero<<<4, 512>>>(bias[0], bias[1], bias[2], bias[3]);
    k_proto<<<15, 256>>>(proto[0], proto[1], proto[2], proto[3]);
    k_text<<<1, 256>>>(text);
    k_pool<<<4096, 256>>>(pooled[0], pooled[1], pooled[2], pooled[3]);
    WPtr wp;
    for (int i = 0; i < 4; i++) { wp.W[i] = W[i]; wp.g[i] = lng[i]; wp.bb[i] = lnb[i]; }
    k_wb<<<240, 256>>>(wp);

    cudaFuncSetAttribute(k_main, cudaFuncAttributeMaxDynamicSharedMemorySize, SM_TOTAL);
    k_main<<<512, 512, SM_TOTAL>>>();
    k_fin<<<256, 256>>>(ls, (float*)d_out);
}

// round 8
// speedup vs baseline: 2.4854x; 1.1327x over previous
#include <cuda_runtime.h>
#include <cuda_bf16.h>
#include <cstdint>
#include <cstring>

#define DI __device__ __forceinline__

// ---------------- static scratch (no allocation allowed) ----------------
__device__ __align__(16) __nv_bfloat16 g_sW[1966080];      // g1*W1 bf16 [C][512] per level
__device__ float g_proto_mean[4 * 2048];
__device__ float g_s2ss2[8];                               // per level: sum, sumsq of proto ctx
__device__ float g_gw[2048], g_bw[2048], g_u2[2048];
__device__ float g_text[4096];                             // l2-normalized text [8][512]
__device__ float g_logits[8192 * 32];                      // [B][4][8] pre-scale logits

__constant__ int cC[4]  = {256, 512, 1024, 2048};
__constant__ int cWO[4] = {0, 131072, 393216, 917504};     // elem offsets into g_sW

// ---------------- PTX helpers ----------------
DI uint32_t su32(const void* p) {
    uint32_t a;
    asm("{ .reg .u64 t; cvta.to.shared.u64 t, %1; cvt.u32.u64 %0, t; }" : "=r"(a) : "l"(p));
    return a;
}
DI void cp16(uint32_t d, const void* s) {
    asm volatile("cp.async.cg.shared.global [%0], [%1], 16;" :: "r"(d), "l"(s));
}
DI void cpcommit() { asm volatile("cp.async.commit_group;"); }
DI void sts64(uint32_t a, uint32_t lo, uint32_t hi) {
    asm volatile("st.shared.v2.b32 [%0], {%1, %2};" :: "r"(a), "r"(lo), "r"(hi) : "memory");
}
DI void ldmA(uint32_t* r, uint32_t a) {
    asm volatile("ldmatrix.sync.aligned.m8n8.x4.shared.b16 {%0,%1,%2,%3}, [%4];"
                 : "=r"(r[0]), "=r"(r[1]), "=r"(r[2]), "=r"(r[3]) : "r"(a));
}
DI void ldmBT(uint32_t* r, uint32_t a) {
    asm volatile("ldmatrix.sync.aligned.m8n8.x4.trans.shared.b16 {%0,%1,%2,%3}, [%4];"
                 : "=r"(r[0]), "=r"(r[1]), "=r"(r[2]), "=r"(r[3]) : "r"(a));
}
DI void mma16816(float* c, const uint32_t* a, const uint32_t* b) {
    asm volatile(
        "mma.sync.aligned.m16n8k16.row.col.f32.bf16.bf16.f32 "
        "{%0,%1,%2,%3}, {%4,%5,%6,%7}, {%8,%9}, {%0,%1,%2,%3};"
        : "+f"(c[0]), "+f"(c[1]), "+f"(c[2]), "+f"(c[3])
        : "r"(a[0]), "r"(a[1]), "r"(a[2]), "r"(a[3]), "r"(b[0]), "r"(b[1]));
}

// ---------------- precompute kernels ----------------
__global__ void k_zero(const float* b0, const float* b1, const float* b2, const float* b3) {
    const float* bs[4] = {b0, b1, b2, b3};
    const int lvl = blockIdx.x, d = threadIdx.x;
    g_gw[lvl * 512 + d] = 0.f;
    g_u2[lvl * 512 + d] = 0.f;
    g_bw[lvl * 512 + d] = bs[lvl][d];
    if (lvl == 0 && d < 8) g_s2ss2[d] = 0.f;
}

__global__ void k_proto(const float* __restrict__ p0, const float* __restrict__ p1,
                        const float* __restrict__ p2, const float* __restrict__ p3) {
    const float* pr[4] = {p0, p1, p2, p3};
    const int cb = blockIdx.x;
    const int lvl = cb < 1 ? 0 : cb < 3 ? 1 : cb < 7 ? 2 : 3;
    const int base4[4] = {0, 1, 3, 7};
    const int C = cC[lvl];
    const int c = (cb - base4[lvl]) * 256 + threadIdx.x;
    const float* P = pr[lvl];
    float s = 0.f;
    #pragma unroll 8
    for (int p = 0; p < 64; p++) s += P[p * C + c];
    const float pm = s * 0.015625f;
    g_proto_mean[lvl * 2048 + c] = pm;
    __shared__ float r1[256], r2[256];
    r1[threadIdx.x] = pm; r2[threadIdx.x] = pm * pm; __syncthreads();
    for (int o = 128; o; o >>= 1) {
        if (threadIdx.x < o) { r1[threadIdx.x] += r1[threadIdx.x + o]; r2[threadIdx.x] += r2[threadIdx.x + o]; }
        __syncthreads();
    }
    if (!threadIdx.x) {
        atomicAdd(&g_s2ss2[lvl * 2], r1[0]);
        atomicAdd(&g_s2ss2[lvl * 2 + 1], r2[0]);
    }
}

__global__ void k_text(const float* __restrict__ tb) {
    const int w = threadIdx.x >> 5, ln = threadIdx.x & 31;
    float4 v[4]; float ss = 0.f;
    #pragma unroll
    for (int j = 0; j < 4; j++) {
        v[j] = *(const float4*)(tb + w * 512 + ln * 4 + j * 128);
        ss += v[j].x * v[j].x + v[j].y * v[j].y + v[j].z * v[j].z + v[j].w * v[j].w;
    }
    #pragma unroll
    for (int o = 16; o; o >>= 1) ss += __shfl_xor_sync(~0u, ss, o);
    const float inv = 1.f / fmaxf(sqrtf(ss), 1e-12f);
    #pragma unroll
    for (int j = 0; j < 4; j++) {
        float4 u = v[j]; u.x *= inv; u.y *= inv; u.z *= inv; u.w *= inv;
        *(float4*)(g_text + w * 512 + ln * 4 + j * 128) = u;
    }
}

struct WPtr { const float* W[4]; const float* g[4]; const float* bb[4]; };

// per 32-row j-chunk (240 blocks): gw/bw/u2 atomics + scaled W1 bf16 [j][512]
__global__ void k_wb(WPtr P) {
    const int cb = blockIdx.x;
    const int lvl = cb < 16 ? 0 : cb < 48 ? 1 : cb < 112 ? 2 : 3;
    const int base4[4] = {0, 16, 48, 112};
    const int j0 = (cb - base4[lvl]) * 32;
    const int C = cC[lvl];
    const int c0 = threadIdx.x * 2;
    const float* W = P.W[lvl];
    const float* gg = P.g[lvl];
    const float* bv = P.bb[lvl];
    float gw0 = 0, gw1 = 0, bw0 = 0, bw1 = 0, u0 = 0, u1 = 0;
    #pragma unroll 4
    for (int jj = 0; jj < 32; jj++) {
        const int j = j0 + jj;
        const float gj = gg[j], bj = bv[j];
        const float2 w2 = *(const float2*)(W + (size_t)j * 512 + c0);
        gw0 = fmaf(gj, w2.x, gw0); gw1 = fmaf(gj, w2.y, gw1);
        bw0 = fmaf(bj, w2.x, bw0); bw1 = fmaf(bj, w2.y, bw1);
        if (j >= C) {
            const float pj = g_proto_mean[lvl * 2048 + (j - C)] * gj;
            u0 = fmaf(pj, w2.x, u0); u1 = fmaf(pj, w2.y, u1);
        } else {
            __nv_bfloat162 h = __floats2bfloat162_rn(gj * w2.x, gj * w2.y);
            uint32_t hu; memcpy(&hu, &h, 4);
            *(uint32_t*)(g_sW + cWO[lvl] + (size_t)j * 512 + c0) = hu;
        }
    }
    atomicAdd(&g_gw[lvl * 512 + c0], gw0);
    atomicAdd(&g_gw[lvl * 512 + c0 + 1], gw1);
    atomicAdd(&g_bw[lvl * 512 + c0], bw0);
    atomicAdd(&g_bw[lvl * 512 + c0 + 1], bw1);
    if (j0 >= C) {
        atomicAdd(&g_u2[lvl * 512 + c0], u0);
        atomicAdd(&g_u2[lvl * 512 + c0 + 1], u1);
    }
}

// ---------------- main fused GEMM + epilogue ----------------
// CTA: 64 rows x 512 cols, BK=32, 16 warps (warp = 32-col slice).
// A: fp32 LDG -> regs -> bf16 STS (fused convert + LN row stats), single 8KB buffer.
// B: 3-stage cp.async, 3 x 32KB.
static constexpr int SM_B = 8192;
static constexpr int SM_TOTAL = 8192 + 3 * 32768;   // 106496 B

struct PPtr { const float* p[4]; };

__global__ void __launch_bounds__(512, 1) k_main(PPtr PA) {
    extern __shared__ char smem[];
    const uint32_t sb = su32(smem);
    const int tid = threadIdx.x, wid = tid >> 5, lane = tid & 31;
    const int lvl = 3 - (blockIdx.x >> 7);      // big levels first
    const int tile = blockIdx.x & 127;
    const int C = cC[lvl];
    const int nch = C >> 5;
    const int row0 = tile * 64;
    const float* Ag = PA.p[lvl] + (size_t)row0 * C;
    const __nv_bfloat16* Bg = g_sW + cWO[lvl];

    // A: thread t -> row t>>3, floats [(t&7)*4, +4) of each 32-wide chunk
    const int arow = tid >> 3, acol = (tid & 7) * 4;
    const float* aSrc = Ag + (size_t)arow * C + acol;
    const uint32_t aDst = sb + arow * 128 + ((acol * 2) ^ ((arow & 7) << 4));

    float acc[4][4][4];
    #pragma unroll
    for (int i = 0; i < 4; i++)
        #pragma unroll
        for (int j = 0; j < 4; j++)
            #pragma unroll
            for (int k = 0; k < 4; k++) acc[i][j][k] = 0.f;

    const int rbase = (lane & 7) + 8 * ((lane >> 3) & 1);
    const int cbmat = (lane >> 4) * 16;
    const int xorv = (rbase & 7) << 4;
    const int cb = wid * 32;

    auto issueB = [&](int ch) {
        const int st = ch % 3;
        const __nv_bfloat16* bp = Bg + (size_t)(ch * 32) * 512;
        #pragma unroll
        for (int i = 0; i < 4; i++) {
            const int c = tid + 512 * i, r = c >> 6, c16 = c & 63;
            cp16(sb + SM_B + st * 32768 + r * 1024 + ((c16 * 16) ^ ((r & 7) << 4)),
                 bp + r * 512 + c16 * 8);
        }
        cpcommit();
    };

    float rs = 0.f, rq = 0.f;       // per-thread partial row stats
    float4 av = *(const float4*)(aSrc);
    issueB(0);
    if (nch > 1) issueB(1);

    for (int ch = 0; ch < nch; ch++) {
        if (ch + 2 < nch) { issueB(ch + 2); asm volatile("cp.async.wait_group 2;"); }
        else if (ch + 1 < nch) { asm volatile("cp.async.wait_group 1;"); }
        else { asm volatile("cp.async.wait_group 0;"); }
        // convert + STS A(ch) from regs, accumulate stats
        {
            rs += av.x + av.y + av.z + av.w;
            rq = fmaf(av.x, av.x, rq); rq = fmaf(av.y, av.y, rq);
            rq = fmaf(av.z, av.z, rq); rq = fmaf(av.w, av.w, rq);
            __nv_bfloat162 h0 = __floats2bfloat162_rn(av.x, av.y);
            __nv_bfloat162 h1 = __floats2bfloat162_rn(av.z, av.w);
            uint32_t lo, hi; memcpy(&lo, &h0, 4); memcpy(&hi, &h1, 4);
            sts64(aDst, lo, hi);
        }
        __syncthreads();
        if (ch + 1 < nch) av = *(const float4*)(aSrc + (ch + 1) * 32);
        const int st = ch % 3;
        const uint32_t sA = sb;
        const uint32_t sB = sb + SM_B + st * 32768;
        #pragma unroll
        for (int ks = 0; ks < 2; ks++) {
            uint32_t bf[2][4], af[4][4];
            #pragma unroll
            for (int np = 0; np < 2; np++)
                ldmBT(bf[np], sB + (ks * 16 + rbase) * 1024 +
                              ((((cb + np * 16) * 2) + cbmat) ^ xorv));
            #pragma unroll
            for (int mt = 0; mt < 4; mt++)
                ldmA(af[mt], sA + (mt * 16 + rbase) * 128 + (((ks * 16) * 2 + cbmat) ^ xorv));
            #pragma unroll
            for (int mt = 0; mt < 4; mt++)
                #pragma unroll
                for (int nt = 0; nt < 4; nt++)
                    mma16816(acc[mt][nt], af[mt], &bf[nt >> 1][(nt & 1) * 2]);
        }
        __syncthreads();
    }

    // -------- epilogue (register-resident; reuses pipeline smem) --------
    float* sf   = (float*)smem;
    float* txs  = sf;                 // [8][512]
    float* u2s  = sf + 4096;
    float* gws  = u2s + 512;
    float* bws  = gws + 512;
    float2* srs = (float2*)(bws + 512);       // [64] (mean, inv)
    float2* sraw = srs + 64;                  // [64] raw (sum, sumsq)
    float* prp  = (float*)(sraw + 64);        // [64 rows][16 warps][9]
    float* rinv = prp + 64 * 16 * 9;          // [64]

    // reduce row stats across the 8 threads of each row (lanes differ in bits 0-2)
    #pragma unroll
    for (int o = 1; o < 8; o <<= 1) {
        rs += __shfl_xor_sync(~0u, rs, o);
        rq += __shfl_xor_sync(~0u, rq, o);
    }
    if ((tid & 7) == 0) sraw[arow] = make_float2(rs, rq);

    for (int i = tid; i < 4096; i += 512) txs[i] = g_text[i];
    if (tid < 512) {
        u2s[tid] = g_u2[lvl * 512 + tid];
        gws[tid] = g_gw[lvl * 512 + tid];
        bws[tid] = g_bw[lvl * 512 + tid];
    }
    __syncthreads();
    if (tid < 64) {
        const float s = sraw[tid].x + g_s2ss2[lvl * 2];
        const float q = sraw[tid].y + g_s2ss2[lvl * 2 + 1];
        const float invN = 1.f / (float)(2 * C);
        const float m = s * invN;
        const float var = q * invN - m * m;
        srs[tid] = make_float2(m, rsqrtf(var + 1e-5f));
    }
    __syncthreads();

    const int rr0 = lane >> 2;
    const int cq = (lane & 3) * 2;
    #pragma unroll
    for (int mt = 0; mt < 4; mt++) {
        const int r0 = mt * 16 + rr0, r1 = r0 + 8;
        const float2 s0 = srs[r0], s1 = srs[r1];
        float ss0 = 0.f, ss1 = 0.f;
        float dk0[8] = {0,0,0,0,0,0,0,0}, dk1[8] = {0,0,0,0,0,0,0,0};
        #pragma unroll
        for (int nt = 0; nt < 4; nt++) {
            const int c = cb + nt * 8 + cq;
            const float u2a = u2s[c], u2b = u2s[c + 1];
            const float gwa = gws[c], gwb = gws[c + 1];
            const float bwa = bws[c], bwb = bws[c + 1];
            const float h0 = fmaxf(s0.y * (acc[mt][nt][0] + u2a - s0.x * gwa) + bwa, 0.f);
            const float h1 = fmaxf(s0.y * (acc[mt][nt][1] + u2b - s0.x * gwb) + bwb, 0.f);
            const float h2 = fmaxf(s1.y * (acc[mt][nt][2] + u2a - s1.x * gwa) + bwa, 0.f);
            const float h3 = fmaxf(s1.y * (acc[mt][nt][3] + u2b - s1.x * gwb) + bwb, 0.f);
            ss0 = fmaf(h0, h0, ss0); ss0 = fmaf(h1, h1, ss0);
            ss1 = fmaf(h2, h2, ss1); ss1 = fmaf(h3, h3, ss1);
            #pragma unroll
            for (int k = 0; k < 8; k++) {
                const float2 t2 = *(const float2*)(txs + k * 512 + c);
                dk0[k] = fmaf(h0, t2.x, dk0[k]); dk0[k] = fmaf(h1, t2.y, dk0[k]);
                dk1[k] = fmaf(h2, t2.x, dk1[k]); dk1[k] = fmaf(h3, t2.y, dk1[k]);
            }
        }
        #pragma unroll
        for (int o = 1; o < 4; o <<= 1) {
            ss0 += __shfl_xor_sync(~0u, ss0, o);
            ss1 += __shfl_xor_sync(~0u, ss1, o);
            #pragma unroll
            for (int k = 0; k < 8; k++) {
                dk0[k] += __shfl_xor_sync(~0u, dk0[k], o);
                dk1[k] += __shfl_xor_sync(~0u, dk1[k], o);
            }
        }
        if ((lane & 3) == 0) {
            float* p0 = prp + (r0 * 16 + wid) * 9;
            float* p1 = prp + (r1 * 16 + wid) * 9;
            p0[0] = ss0; p1[0] = ss1;
            #pragma unroll
            for (int k = 0; k < 8; k++) { p0[1 + k] = dk0[k]; p1[1 + k] = dk1[k]; }
        }
    }
    __syncthreads();
    if (tid < 64) {
        float ss = 0.f;
        #pragma unroll
        for (int w = 0; w < 16; w++) ss += prp[(tid * 16 + w) * 9];
        rinv[tid] = 1.f / fmaxf(sqrtf(ss), 1e-12f);
    }
    __syncthreads();
    {
        const int row = tid >> 3, k = tid & 7;
        float d = 0.f;
        #pragma unroll
        for (int w = 0; w < 16; w++) d += prp[(row * 16 + w) * 9 + 1 + k];
        g_logits[(size_t)(row0 + row) * 32 + lvl * 8 + k] = d * rinv[row];
    }
}

// ---------------- final softmax over L ----------------
__global__ void k_fin(const float* __restrict__ ls, float* __restrict__ out) {
    const int i = blockIdx.x * 256 + threadIdx.x;  // b*8 + k
    const float s = fmaxf(ls[0], 1e-4f) * 0.044194173824159216f;  // clip * 1/sqrt(512)
    const int b = i >> 3, k = i & 7;
    float z[4], mx = -1e30f;
    #pragma unroll
    for (int l = 0; l < 4; l++) {
        z[l] = g_logits[b * 32 + l * 8 + k] * s;
        mx = fmaxf(mx, z[l]);
    }
    float e[4], sum = 0.f;
    #pragma unroll
    for (int l = 0; l < 4; l++) { e[l] = expf(z[l] - mx); sum += e[l]; }
    const float inv = 1.f / sum;
    #pragma unroll
    for (int l = 0; l < 4; l++) out[i * 4 + l] = e[l] * inv;
}

// ---------------- launch ----------------
extern "C" void kernel_launch(void* const* d_in, const int* in_sizes, int n_in,
                              void* d_out, int out_size) {
    const float *pooled[4], *proto[4], *lng[4], *lnb[4], *W[4], *bias[4];
    const bool interleaved = (in_sizes[1] == 16384);  // proto_0 = 64*256
    for (int i = 0; i < 4; i++) {
        if (interleaved) {
            pooled[i] = (const float*)d_in[6 * i + 0];
            proto[i]  = (const float*)d_in[6 * i + 1];
            lng[i]    = (const float*)d_in[6 * i + 2];
            lnb[i]    = (const float*)d_in[6 * i + 3];
            W[i]      = (const float*)d_in[6 * i + 4];
            bias[i]   = (const float*)d_in[6 * i + 5];
        } else {
            pooled[i] = (const float*)d_in[i];
            proto[i]  = (const float*)d_in[4 + i];
            lng[i]    = (const float*)d_in[8 + i];
            lnb[i]    = (const float*)d_in[12 + i];
            W[i]      = (const float*)d_in[16 + i];
            bias[i]   = (const float*)d_in[20 + i];
        }
    }
    const float* text = (const float*)d_in[24];
    const float* ls   = (const float*)d_in[25];

    k_zero<<<4, 512>>>(bias[0], bias[1], bias[2], bias[3]);
    k_proto<<<15, 256>>>(proto[0], proto[1], proto[2], proto[3]);
    k_text<<<1, 256>>>(text);
    WPtr wp;
    for (int i = 0; i < 4; i++) { wp.W[i] = W[i]; wp.g[i] = lng[i]; wp.bb[i] = lnb[i]; }
    k_wb<<<240, 256>>>(wp);

    PPtr pa;
    for (int i = 0; i < 4; i++) pa.p[i] = pooled[i];
    cudaFuncSetAttribute(k_main, cudaFuncAttributeMaxDynamicSharedMemorySize, SM_TOTAL);
    k_main<<<512, 512, SM_TOTAL>>>(pa);
    k_fin<<<256, 256>>>(ls, (float*)d_out);
}

// round 9
// speedup vs baseline: 2.5274x; 1.0169x over previous
#include <cuda_runtime.h>
#include <cuda_bf16.h>
#include <cstdint>
#include <cstring>

#define DI __device__ __forceinline__

// ---------------- static scratch (no allocation allowed) ----------------
__device__ __align__(16) __nv_bfloat16 g_sW[1966080];      // g1*W1 bf16 [C][512] per level
__device__ float g_proto_mean[4 * 2048];
__device__ float g_s2ss2[8];                               // per level: sum, sumsq of proto ctx
__device__ float g_gw[2048], g_bw[2048], g_u2[2048];
__device__ float g_text[4096];                             // l2-normalized text [8][512]
__device__ float g_logits[8192 * 32];                      // [B][4][8] pre-scale logits

__constant__ int cC[4]  = {256, 512, 1024, 2048};
__constant__ int cWO[4] = {0, 131072, 393216, 917504};     // elem offsets into g_sW

// ---------------- PTX helpers ----------------
DI uint32_t su32(const void* p) {
    uint32_t a;
    asm("{ .reg .u64 t; cvta.to.shared.u64 t, %1; cvt.u32.u64 %0, t; }" : "=r"(a) : "l"(p));
    return a;
}
DI void cp16(uint32_t d, const void* s) {
    asm volatile("cp.async.cg.shared.global [%0], [%1], 16;" :: "r"(d), "l"(s));
}
DI void cpcommit() { asm volatile("cp.async.commit_group;"); }
DI void sts64(uint32_t a, uint32_t lo, uint32_t hi) {
    asm volatile("st.shared.v2.b32 [%0], {%1, %2};" :: "r"(a), "r"(lo), "r"(hi) : "memory");
}
DI void ldmA(uint32_t* r, uint32_t a) {
    asm volatile("ldmatrix.sync.aligned.m8n8.x4.shared.b16 {%0,%1,%2,%3}, [%4];"
                 : "=r"(r[0]), "=r"(r[1]), "=r"(r[2]), "=r"(r[3]) : "r"(a));
}
DI void ldmBT(uint32_t* r, uint32_t a) {
    asm volatile("ldmatrix.sync.aligned.m8n8.x4.trans.shared.b16 {%0,%1,%2,%3}, [%4];"
                 : "=r"(r[0]), "=r"(r[1]), "=r"(r[2]), "=r"(r[3]) : "r"(a));
}
DI void mma16816(float* c, const uint32_t* a, const uint32_t* b) {
    asm volatile(
        "mma.sync.aligned.m16n8k16.row.col.f32.bf16.bf16.f32 "
        "{%0,%1,%2,%3}, {%4,%5,%6,%7}, {%8,%9}, {%0,%1,%2,%3};"
        : "+f"(c[0]), "+f"(c[1]), "+f"(c[2]), "+f"(c[3])
        : "r"(a[0]), "r"(a[1]), "r"(a[2]), "r"(a[3]), "r"(b[0]), "r"(b[1]));
}

// ---------------- precompute kernels ----------------
__global__ void k_zero(const float* b0, const float* b1, const float* b2, const float* b3) {
    const float* bs[4] = {b0, b1, b2, b3};
    const int lvl = blockIdx.x, d = threadIdx.x;
    g_gw[lvl * 512 + d] = 0.f;
    g_u2[lvl * 512 + d] = 0.f;
    g_bw[lvl * 512 + d] = bs[lvl][d];
    if (lvl == 0 && d < 8) g_s2ss2[d] = 0.f;
}

__global__ void k_proto(const float* __restrict__ p0, const float* __restrict__ p1,
                        const float* __restrict__ p2, const float* __restrict__ p3) {
    const float* pr[4] = {p0, p1, p2, p3};
    const int cb = blockIdx.x;
    const int lvl = cb < 1 ? 0 : cb < 3 ? 1 : cb < 7 ? 2 : 3;
    const int base4[4] = {0, 1, 3, 7};
    const int C = cC[lvl];
    const int c = (cb - base4[lvl]) * 256 + threadIdx.x;
    const float* P = pr[lvl];
    float s = 0.f;
    #pragma unroll 8
    for (int p = 0; p < 64; p++) s += P[p * C + c];
    const float pm = s * 0.015625f;
    g_proto_mean[lvl * 2048 + c] = pm;
    __shared__ float r1[256], r2[256];
    r1[threadIdx.x] = pm; r2[threadIdx.x] = pm * pm; __syncthreads();
    for (int o = 128; o; o >>= 1) {
        if (threadIdx.x < o) { r1[threadIdx.x] += r1[threadIdx.x + o]; r2[threadIdx.x] += r2[threadIdx.x + o]; }
        __syncthreads();
    }
    if (!threadIdx.x) {
        atomicAdd(&g_s2ss2[lvl * 2], r1[0]);
        atomicAdd(&g_s2ss2[lvl * 2 + 1], r2[0]);
    }
}

__global__ void k_text(const float* __restrict__ tb) {
    const int w = threadIdx.x >> 5, ln = threadIdx.x & 31;
    float4 v[4]; float ss = 0.f;
    #pragma unroll
    for (int j = 0; j < 4; j++) {
        v[j] = *(const float4*)(tb + w * 512 + ln * 4 + j * 128);
        ss += v[j].x * v[j].x + v[j].y * v[j].y + v[j].z * v[j].z + v[j].w * v[j].w;
    }
    #pragma unroll
    for (int o = 16; o; o >>= 1) ss += __shfl_xor_sync(~0u, ss, o);
    const float inv = 1.f / fmaxf(sqrtf(ss), 1e-12f);
    #pragma unroll
    for (int j = 0; j < 4; j++) {
        float4 u = v[j]; u.x *= inv; u.y *= inv; u.z *= inv; u.w *= inv;
        *(float4*)(g_text + w * 512 + ln * 4 + j * 128) = u;
    }
}

struct WPtr { const float* W[4]; const float* g[4]; const float* bb[4]; };

// 480 blocks x 512 threads; block = 16 j-rows, thread = 8 rows x 2 cols micro-tile.
// gw/bw/u2 partials: smem half-reduce then one atomicAdd per column per block.
__global__ void k_wb(WPtr P) {
    __shared__ float red[256 * 6];
    const int cb = blockIdx.x;
    const int lvl = cb < 32 ? 0 : cb < 96 ? 1 : cb < 224 ? 2 : 3;
    const int base4[4] = {0, 32, 96, 224};
    const int j0 = (cb - base4[lvl]) * 16;
    const int C = cC[lvl];
    const int half = threadIdx.x >> 8;      // 0/1 -> rows j0..j0+7 / j0+8..j0+15
    const int ci = threadIdx.x & 255;
    const int c0 = ci * 2;
    const int jb = j0 + half * 8;
    const float* W = P.W[lvl];
    const float* gg = P.g[lvl];
    const float* bv = P.bb[lvl];
    float gw0 = 0, gw1 = 0, bw0 = 0, bw1 = 0, u0 = 0, u1 = 0;
    uint32_t outw[8];
    #pragma unroll
    for (int jj = 0; jj < 8; jj++) {
        const int j = jb + jj;
        const float gj = gg[j], bj = bv[j];
        const float2 w2 = *(const float2*)(W + (size_t)j * 512 + c0);
        gw0 = fmaf(gj, w2.x, gw0); gw1 = fmaf(gj, w2.y, gw1);
        bw0 = fmaf(bj, w2.x, bw0); bw1 = fmaf(bj, w2.y, bw1);
        if (j0 >= C) {
            const float pj = g_proto_mean[lvl * 2048 + (j - C)] * gj;
            u0 = fmaf(pj, w2.x, u0); u1 = fmaf(pj, w2.y, u1);
        } else {
            __nv_bfloat162 h = __floats2bfloat162_rn(gj * w2.x, gj * w2.y);
            memcpy(&outw[jj], &h, 4);
        }
    }
    if (j0 < C) {
        #pragma unroll
        for (int jj = 0; jj < 8; jj++)
            *(uint32_t*)(g_sW + cWO[lvl] + (size_t)(jb + jj) * 512 + c0) = outw[jj];
    }
    if (half) {
        float* r = red + ci * 6;
        r[0] = gw0; r[1] = gw1; r[2] = bw0; r[3] = bw1; r[4] = u0; r[5] = u1;
    }
    __syncthreads();
    if (!half) {
        const float* r = red + ci * 6;
        gw0 += r[0]; gw1 += r[1]; bw0 += r[2]; bw1 += r[3]; u0 += r[4]; u1 += r[5];
        atomicAdd(&g_gw[lvl * 512 + c0], gw0);
        atomicAdd(&g_gw[lvl * 512 + c0 + 1], gw1);
        atomicAdd(&g_bw[lvl * 512 + c0], bw0);
        atomicAdd(&g_bw[lvl * 512 + c0 + 1], bw1);
        if (j0 >= C) {
            atomicAdd(&g_u2[lvl * 512 + c0], u0);
            atomicAdd(&g_u2[lvl * 512 + c0 + 1], u1);
        }
    }
}

// ---------------- main fused GEMM + epilogue ----------------
// CTA: 64 rows x 512 cols, BK=32, 16 warps (warp = 32-col slice).
// A: fp32 LDG -> regs -> bf16 STS (fused convert + LN stats), 2 x 8KB buffers.
// B: 4-stage cp.async ring, 4 x 32KB. ONE __syncthreads per K-chunk.
static constexpr int SM_B = 16384;
static constexpr int SM_TOTAL = 16384 + 4 * 32768;   // 147456 B

struct PPtr { const float* p[4]; };

__global__ void __launch_bounds__(512, 1) k_main(PPtr PA) {
    extern __shared__ char smem[];
    const uint32_t sb = su32(smem);
    const int tid = threadIdx.x, wid = tid >> 5, lane = tid & 31;
    const int lvl = 3 - (blockIdx.x >> 7);      // big levels first
    const int tile = blockIdx.x & 127;
    const int C = cC[lvl];
    const int nch = C >> 5;
    const int row0 = tile * 64;
    const float* Ag = PA.p[lvl] + (size_t)row0 * C;
    const __nv_bfloat16* Bg = g_sW + cWO[lvl];

    // A: thread t -> row t>>3, floats [(t&7)*4, +4) of each 32-wide chunk
    const int arow = tid >> 3, acol = (tid & 7) * 4;
    const float* aSrc = Ag + (size_t)arow * C + acol;
    const uint32_t aDst = sb + arow * 128 + ((acol * 2) ^ ((arow & 7) << 4));

    float acc[4][4][4];
    #pragma unroll
    for (int i = 0; i < 4; i++)
        #pragma unroll
        for (int j = 0; j < 4; j++)
            #pragma unroll
            for (int k = 0; k < 4; k++) acc[i][j][k] = 0.f;

    const int rbase = (lane & 7) + 8 * ((lane >> 3) & 1);
    const int cbmat = (lane >> 4) * 16;
    const int xorv = (rbase & 7) << 4;
    const int cb = wid * 32;

    auto issueB = [&](int ch) {
        const int st = ch & 3;
        const __nv_bfloat16* bp = Bg + (size_t)(ch * 32) * 512;
        #pragma unroll
        for (int i = 0; i < 4; i++) {
            const int c = tid + 512 * i, r = c >> 6, c16 = c & 63;
            cp16(sb + SM_B + st * 32768 + r * 1024 + ((c16 * 16) ^ ((r & 7) << 4)),
                 bp + r * 512 + c16 * 8);
        }
        cpcommit();
    };

    float rs = 0.f, rq = 0.f;       // per-thread partial row stats
    float4 av = *(const float4*)(aSrc);
    issueB(0);
    if (nch > 1) issueB(1);
    if (nch > 2) issueB(2);

    for (int ch = 0; ch < nch; ch++) {
        if (ch + 2 < nch)      asm volatile("cp.async.wait_group 2;");
        else if (ch + 1 < nch) asm volatile("cp.async.wait_group 1;");
        else                   asm volatile("cp.async.wait_group 0;");
        // convert + STS A(ch) from regs, accumulate stats
        {
            rs += av.x + av.y + av.z + av.w;
            rq = fmaf(av.x, av.x, rq); rq = fmaf(av.y, av.y, rq);
            rq = fmaf(av.z, av.z, rq); rq = fmaf(av.w, av.w, rq);
            __nv_bfloat162 h0 = __floats2bfloat162_rn(av.x, av.y);
            __nv_bfloat162 h1 = __floats2bfloat162_rn(av.z, av.w);
            uint32_t lo, hi; memcpy(&lo, &h0, 4); memcpy(&hi, &h1, 4);
            sts64(aDst + (ch & 1) * 8192, lo, hi);
        }
        __syncthreads();            // the ONLY barrier per chunk
        if (ch + 3 < nch) issueB(ch + 3);
        if (ch + 1 < nch) av = *(const float4*)(aSrc + (ch + 1) * 32);
        const uint32_t sA = sb + (ch & 1) * 8192;
        const uint32_t sB = sb + SM_B + (ch & 3) * 32768;
        #pragma unroll
        for (int ks = 0; ks < 2; ks++) {
            uint32_t bf[2][4], af[4][4];
            #pragma unroll
            for (int np = 0; np < 2; np++)
                ldmBT(bf[np], sB + (ks * 16 + rbase) * 1024 +
                              ((((cb + np * 16) * 2) + cbmat) ^ xorv));
            #pragma unroll
            for (int mt = 0; mt < 4; mt++)
                ldmA(af[mt], sA + (mt * 16 + rbase) * 128 + (((ks * 16) * 2 + cbmat) ^ xorv));
            #pragma unroll
            for (int mt = 0; mt < 4; mt++)
                #pragma unroll
                for (int nt = 0; nt < 4; nt++)
                    mma16816(acc[mt][nt], af[mt], &bf[nt >> 1][(nt & 1) * 2]);
        }
    }
    __syncthreads();                // mainloop smem reads done before epilogue reuse

    // -------- epilogue (register-resident; reuses pipeline smem) --------
    float* sf   = (float*)smem;
    float* txs  = sf;                 // [8][512]
    float* u2s  = sf + 4096;
    float* gws  = u2s + 512;
    float* bws  = gws + 512;
    float2* srs = (float2*)(bws + 512);       // [64] (mean, inv)
    float2* sraw = srs + 64;                  // [64] raw (sum, sumsq)
    float* prp  = (float*)(sraw + 64);        // [64 rows][16 warps][9]
    float* rinv = prp + 64 * 16 * 9;          // [64]

    // reduce row stats across the 8 threads of each row (lanes differ in bits 0-2)
    #pragma unroll
    for (int o = 1; o < 8; o <<= 1) {
        rs += __shfl_xor_sync(~0u, rs, o);
        rq += __shfl_xor_sync(~0u, rq, o);
    }
    if ((tid & 7) == 0) sraw[arow] = make_float2(rs, rq);

    for (int i = tid; i < 4096; i += 512) txs[i] = g_text[i];
    if (tid < 512) {
        u2s[tid] = g_u2[lvl * 512 + tid];
        gws[tid] = g_gw[lvl * 512 + tid];
        bws[tid] = g_bw[lvl * 512 + tid];
    }
    __syncthreads();
    if (tid < 64) {
        const float s = sraw[tid].x + g_s2ss2[lvl * 2];
        const float q = sraw[tid].y + g_s2ss2[lvl * 2 + 1];
        const float invN = 1.f / (float)(2 * C);
        const float m = s * invN;
        const float var = q * invN - m * m;
        srs[tid] = make_float2(m, rsqrtf(var + 1e-5f));
    }
    __syncthreads();

    const int rr0 = lane >> 2;
    const int cq = (lane & 3) * 2;
    #pragma unroll
    for (int mt = 0; mt < 4; mt++) {
        const int r0 = mt * 16 + rr0, r1 = r0 + 8;
        const float2 s0 = srs[r0], s1 = srs[r1];
        float ss0 = 0.f, ss1 = 0.f;
        float dk0[8] = {0,0,0,0,0,0,0,0}, dk1[8] = {0,0,0,0,0,0,0,0};
        #pragma unroll
        for (int nt = 0; nt < 4; nt++) {
            const int c = cb + nt * 8 + cq;
            const float u2a = u2s[c], u2b = u2s[c + 1];
            const float gwa = gws[c], gwb = gws[c + 1];
            const float bwa = bws[c], bwb = bws[c + 1];
            const float h0 = fmaxf(s0.y * (acc[mt][nt][0] + u2a - s0.x * gwa) + bwa, 0.f);
            const float h1 = fmaxf(s0.y * (acc[mt][nt][1] + u2b - s0.x * gwb) + bwb, 0.f);
            const float h2 = fmaxf(s1.y * (acc[mt][nt][2] + u2a - s1.x * gwa) + bwa, 0.f);
            const float h3 = fmaxf(s1.y * (acc[mt][nt][3] + u2b - s1.x * gwb) + bwb, 0.f);
            ss0 = fmaf(h0, h0, ss0); ss0 = fmaf(h1, h1, ss0);
            ss1 = fmaf(h2, h2, ss1); ss1 = fmaf(h3, h3, ss1);
            #pragma unroll
            for (int k = 0; k < 8; k++) {
                const float2 t2 = *(const float2*)(txs + k * 512 + c);
                dk0[k] = fmaf(h0, t2.x, dk0[k]); dk0[k] = fmaf(h1, t2.y, dk0[k]);
                dk1[k] = fmaf(h2, t2.x, dk1[k]); dk1[k] = fmaf(h3, t2.y, dk1[k]);
            }
        }
        #pragma unroll
        for (int o = 1; o < 4; o <<= 1) {
            ss0 += __shfl_xor_sync(~0u, ss0, o);
            ss1 += __shfl_xor_sync(~0u, ss1, o);
            #pragma unroll
            for (int k = 0; k < 8; k++) {
                dk0[k] += __shfl_xor_sync(~0u, dk0[k], o);
                dk1[k] += __shfl_xor_sync(~0u, dk1[k], o);
            }
        }
        if ((lane & 3) == 0) {
            float* p0 = prp + (r0 * 16 + wid) * 9;
            float* p1 = prp + (r1 * 16 + wid) * 9;
            p0[0] = ss0; p1[0] = ss1;
            #pragma unroll
            for (int k = 0; k < 8; k++) { p0[1 + k] = dk0[k]; p1[1 + k] = dk1[k]; }
        }
    }
    __syncthreads();
    if (tid < 64) {
        float ss = 0.f;
        #pragma unroll
        for (int w = 0; w < 16; w++) ss += prp[(tid * 16 + w) * 9];
        rinv[tid] = 1.f / fmaxf(sqrtf(ss), 1e-12f);
    }
    __syncthreads();
    {
        const int row = tid >> 3, k = tid & 7;
        float d = 0.f;
        #pragma unroll
        for (int w = 0; w < 16; w++) d += prp[(row * 16 + w) * 9 + 1 + k];
        g_logits[(size_t)(row0 + row) * 32 + lvl * 8 + k] = d * rinv[row];
    }
}

// ---------------- final softmax over L ----------------
__global__ void k_fin(const float* __restrict__ ls, float* __restrict__ out) {
    const int i = blockIdx.x * 256 + threadIdx.x;  // b*8 + k
    const float s = fmaxf(ls[0], 1e-4f) * 0.044194173824159216f;  // clip * 1/sqrt(512)
    const int b = i >> 3, k = i & 7;
    float z[4], mx = -1e30f;
    #pragma unroll
    for (int l = 0; l < 4; l++) {
        z[l] = g_logits[b * 32 + l * 8 + k] * s;
        mx = fmaxf(mx, z[l]);
    }
    float e[4], sum = 0.f;
    #pragma unroll
    for (int l = 0; l < 4; l++) { e[l] = expf(z[l] - mx); sum += e[l]; }
    const float inv = 1.f / sum;
    #pragma unroll
    for (int l = 0; l < 4; l++) out[i * 4 + l] = e[l] * inv;
}

// ---------------- launch ----------------
extern "C" void kernel_launch(void* const* d_in, const int* in_sizes, int n_in,
                              void* d_out, int out_size) {
    const float *pooled[4], *proto[4], *lng[4], *lnb[4], *W[4], *bias[4];
    const bool interleaved = (in_sizes[1] == 16384);  // proto_0 = 64*256
    for (int i = 0; i < 4; i++) {
        if (interleaved) {
            pooled[i] = (const float*)d_in[6 * i + 0];
            proto[i]  = (const float*)d_in[6 * i + 1];
            lng[i]    = (const float*)d_in[6 * i + 2];
            lnb[i]    = (const float*)d_in[6 * i + 3];
            W[i]      = (const float*)d_in[6 * i + 4];
            bias[i]   = (const float*)d_in[6 * i + 5];
        } else {
            pooled[i] = (const float*)d_in[i];
            proto[i]  = (const float*)d_in[4 + i];
            lng[i]    = (const float*)d_in[8 + i];
            lnb[i]    = (const float*)d_in[12 + i];
            W[i]      = (const float*)d_in[16 + i];
            bias[i]   = (const float*)d_in[20 + i];
        }
    }
    const float* text = (const float*)d_in[24];
    const float* ls   = (const float*)d_in[25];

    k_zero<<<4, 512>>>(bias[0], bias[1], bias[2], bias[3]);
    k_proto<<<15, 256>>>(proto[0], proto[1], proto[2], proto[3]);
    k_text<<<1, 256>>>(text);
    WPtr wp;
    for (int i = 0; i < 4; i++) { wp.W[i] = W[i]; wp.g[i] = lng[i]; wp.bb[i] = lnb[i]; }
    k_wb<<<480, 512>>>(wp);

    PPtr pa;
    for (int i = 0; i < 4; i++) pa.p[i] = pooled[i];
    cudaFuncSetAttribute(k_main, cudaFuncAttributeMaxDynamicSharedMemorySize, SM_TOTAL);
    k_main<<<512, 512, SM_TOTAL>>>(pa);
    k_fin<<<256, 256>>>(ls, (float*)d_out);
}